// round 6
// baseline (speedup 1.0000x reference)
#include <cuda_runtime.h>
#include <cuda_fp16.h>
#include <stdint.h>

#define NMAX 50000
#define EMAX 600000

typedef unsigned long long ull;

// ---------------- CSR scratch ----------------
__device__ int g_rowptr[3][NMAX + 1];
__device__ int g_cursor[3][NMAX];
__device__ int g_esrc[3][EMAX];

// ---------------- fp16 payload buffers ----------------
__device__ __half g_xh_d[(size_t)NMAX * 128];   // x_drug fp16
__device__ __half g_xh_p[(size_t)NMAX * 128];   // x_prot fp16
__device__ __half g_th[3][(size_t)NMAX * 64];   // layer-2 transformed, fp16

// ---------------- fp32 scratch ----------------
constexpr size_t F_HD    = 0;                                  // [ND,128]
constexpr size_t F_HP    = F_HD + (size_t)NMAX * 128;          // [NP,128]
constexpr size_t F_TOTAL = F_HP + (size_t)NMAX * 128;
__device__ float g_fs[F_TOTAL];

// ---------------- packed f32x2 helpers ----------------
__device__ __forceinline__ ull ffma2(ull a, ull b, ull c) {
    ull d;
    asm("fma.rn.f32x2 %0, %1, %2, %3;" : "=l"(d) : "l"(a), "l"(b), "l"(c));
    return d;
}
__device__ __forceinline__ ull pack2(float lo, float hi) {
    ull d;
    asm("mov.b64 %0, {%1, %2};" : "=l"(d) : "f"(lo), "f"(hi));
    return d;
}
__device__ __forceinline__ void unpack2(ull v, float& lo, float& hi) {
    asm("mov.b64 {%0, %1}, %2;" : "=f"(lo), "=f"(hi) : "l"(v));
}

__device__ __forceinline__ float4 h2f4(uint2 u) {
    __half2 a = *reinterpret_cast<__half2*>(&u.x);
    __half2 b = *reinterpret_cast<__half2*>(&u.y);
    float2 fa = __half22float2(a);
    float2 fb = __half22float2(b);
    return make_float4(fa.x, fa.y, fb.x, fb.y);
}
__device__ __forceinline__ float2 h2f2(unsigned int u) {
    __half2 a = *reinterpret_cast<__half2*>(&u);
    return __half22float2(a);
}

// ---------------- fp32 -> fp16 conversion ----------------
__global__ void k_tohalf(const float* __restrict__ xd, const float* __restrict__ xp,
                         int nd4, int np4) {
    int i = blockIdx.x * blockDim.x + threadIdx.x;
    int stride = gridDim.x * blockDim.x;
    uint2* od = reinterpret_cast<uint2*>(g_xh_d);
    uint2* op = reinterpret_cast<uint2*>(g_xh_p);
    for (int j = i; j < nd4; j += stride) {
        float4 v = __ldg(reinterpret_cast<const float4*>(xd) + j);
        __half2 a = __floats2half2_rn(v.x, v.y);
        __half2 b = __floats2half2_rn(v.z, v.w);
        uint2 o;
        o.x = *reinterpret_cast<unsigned int*>(&a);
        o.y = *reinterpret_cast<unsigned int*>(&b);
        od[j] = o;
    }
    for (int j = i; j < np4; j += stride) {
        float4 v = __ldg(reinterpret_cast<const float4*>(xp) + j);
        __half2 a = __floats2half2_rn(v.x, v.y);
        __half2 b = __floats2half2_rn(v.z, v.w);
        uint2 o;
        o.x = *reinterpret_cast<unsigned int*>(&a);
        o.y = *reinterpret_cast<unsigned int*>(&b);
        op[j] = o;
    }
}

// ---------------- CSR build ----------------

__global__ void k_zero_counts() {
    int i = blockIdx.x * blockDim.x + threadIdx.x;
    int total = 3 * (NMAX + 1);
    int stride = gridDim.x * blockDim.x;
    int* p = &g_rowptr[0][0];
    for (; i < total; i += stride) p[i] = 0;
}

__global__ void k_count(const int* __restrict__ d0, int e0,
                        const int* __restrict__ d1, int e1,
                        const int* __restrict__ d2, int e2) {
    int i = blockIdx.x * blockDim.x + threadIdx.x;
    int stride = gridDim.x * blockDim.x;
    for (int j = i; j < e0; j += stride) atomicAdd(&g_rowptr[0][__ldg(d0 + j)], 1);
    for (int j = i; j < e1; j += stride) atomicAdd(&g_rowptr[1][__ldg(d1 + j)], 1);
    for (int j = i; j < e2; j += stride) atomicAdd(&g_rowptr[2][__ldg(d2 + j)], 1);
}

__global__ void k_scan(int n0, int n1, int n2) {
    int rel = blockIdx.x;
    int n = (rel == 0) ? n0 : ((rel == 1) ? n1 : n2);
    int* cnt = g_rowptr[rel];
    int* cur = g_cursor[rel];
    __shared__ int sh[1024];
    int tid = threadIdx.x;
    int chunk = (n + 1023) >> 10;
    int lo = tid * chunk;
    int hi = lo + chunk;
    if (hi > n) hi = n;
    int tsum = 0;
    for (int i = lo; i < hi; i++) tsum += cnt[i];
    sh[tid] = tsum;
    __syncthreads();
    for (int off = 1; off < 1024; off <<= 1) {
        int v = (tid >= off) ? sh[tid - off] : 0;
        __syncthreads();
        sh[tid] += v;
        __syncthreads();
    }
    int run = (tid > 0) ? sh[tid - 1] : 0;
    for (int i = lo; i < hi; i++) {
        int c = cnt[i];
        cnt[i] = run;
        cur[i] = run;
        run += c;
    }
    if (tid == 0) cnt[n] = sh[1023];
}

__global__ void k_fill3(const int* __restrict__ s0, const int* __restrict__ d0, int e0,
                        const int* __restrict__ s1, const int* __restrict__ d1, int e1,
                        const int* __restrict__ s2, const int* __restrict__ d2, int e2) {
    int i = blockIdx.x * blockDim.x + threadIdx.x;
    int stride = gridDim.x * blockDim.x;
    for (int e = i; e < e0; e += stride) {
        int pos = atomicAdd(&g_cursor[0][__ldg(d0 + e)], 1);
        g_esrc[0][pos] = __ldg(s0 + e);
    }
    for (int e = i; e < e1; e += stride) {
        int pos = atomicAdd(&g_cursor[1][__ldg(d1 + e)], 1);
        g_esrc[1][pos] = __ldg(s1 + e);
    }
    for (int e = i; e < e2; e += stride) {
        int pos = atomicAdd(&g_cursor[2][__ldg(d2 + e)], 1);
        g_esrc[2][pos] = __ldg(s2 + e);
    }
}

// ---------------- pair-interleaved fp16 gathers ----------------
// Two nodes per warp, predicated unroll-4 -> 8 independent loads in flight.

__device__ __forceinline__ void gpair128h(const int* __restrict__ es,
                                          const __half* __restrict__ x,
                                          int b0, int d0, int b1, int d1, int lane,
                                          float4& o0, float4& o1) {
    float4 a0 = make_float4(0.f, 0.f, 0.f, 0.f);
    float4 a1 = make_float4(0.f, 0.f, 0.f, 0.f);
    int m = d0 > d1 ? d0 : d1;
    for (int e = 0; e < m; e += 4) {
        uint2 v0[4], v1[4];
        bool q0[4], q1[4];
#pragma unroll
        for (int j = 0; j < 4; j++) {
            q0[j] = (e + j) < d0;
            q1[j] = (e + j) < d1;
            int s0 = q0[j] ? __ldg(es + b0 + e + j) : 0;
            int s1 = q1[j] ? __ldg(es + b1 + e + j) : 0;
            v0[j] = q0[j] ? __ldg(reinterpret_cast<const uint2*>(x + (size_t)s0 * 128) + lane)
                          : make_uint2(0u, 0u);
            v1[j] = q1[j] ? __ldg(reinterpret_cast<const uint2*>(x + (size_t)s1 * 128) + lane)
                          : make_uint2(0u, 0u);
        }
#pragma unroll
        for (int j = 0; j < 4; j++) {
            if (q0[j]) {
                float4 f = h2f4(v0[j]);
                a0.x += f.x; a0.y += f.y; a0.z += f.z; a0.w += f.w;
            }
            if (q1[j]) {
                float4 f = h2f4(v1[j]);
                a1.x += f.x; a1.y += f.y; a1.z += f.z; a1.w += f.w;
            }
        }
    }
    float i0 = 1.0f / fmaxf((float)d0, 1.0f);
    float i1 = 1.0f / fmaxf((float)d1, 1.0f);
    o0 = make_float4(a0.x * i0, a0.y * i0, a0.z * i0, a0.w * i0);
    o1 = make_float4(a1.x * i1, a1.y * i1, a1.z * i1, a1.w * i1);
}

__device__ __forceinline__ void gpair64h(const int* __restrict__ es,
                                         const __half* __restrict__ x,
                                         int b0, int d0, int b1, int d1, int lane,
                                         float2& o0, float2& o1) {
    float2 a0 = make_float2(0.f, 0.f);
    float2 a1 = make_float2(0.f, 0.f);
    int m = d0 > d1 ? d0 : d1;
    for (int e = 0; e < m; e += 4) {
        unsigned int v0[4], v1[4];
        bool q0[4], q1[4];
#pragma unroll
        for (int j = 0; j < 4; j++) {
            q0[j] = (e + j) < d0;
            q1[j] = (e + j) < d1;
            int s0 = q0[j] ? __ldg(es + b0 + e + j) : 0;
            int s1 = q1[j] ? __ldg(es + b1 + e + j) : 0;
            v0[j] = q0[j] ? __ldg(reinterpret_cast<const unsigned int*>(x + (size_t)s0 * 64) + lane)
                          : 0u;
            v1[j] = q1[j] ? __ldg(reinterpret_cast<const unsigned int*>(x + (size_t)s1 * 64) + lane)
                          : 0u;
        }
#pragma unroll
        for (int j = 0; j < 4; j++) {
            if (q0[j]) {
                float2 f = h2f2(v0[j]);
                a0.x += f.x; a0.y += f.y;
            }
            if (q1[j]) {
                float2 f = h2f2(v1[j]);
                a1.x += f.x; a1.y += f.y;
            }
        }
    }
    float i0 = 1.0f / fmaxf((float)d0, 1.0f);
    float i1 = 1.0f / fmaxf((float)d1, 1.0f);
    o0 = make_float2(a0.x * i0, a0.y * i0);
    o1 = make_float2(a1.x * i1, a1.y * i1);
}

__device__ __forceinline__ void node_range(const int* __restrict__ ptr, int node, int n,
                                           int& b, int& d) {
    if (node < n) {
        b = ptr[node];
        d = ptr[node + 1] - b;
    } else {
        b = 0; d = 0;
    }
}

// ---------------- merged fused layer-1 ----------------
// 256 threads, 16 dst rows per block. Gather: warp w -> local rows 2w, 2w+1.
// GEMM: j = tid&127, half-block handles 8 rows.

__global__ void __launch_bounds__(256, 3)
k_l1(const float* __restrict__ W1_ddi, const float* __restrict__ b1_ddi,
     const float* __restrict__ W1_dpi, const float* __restrict__ b1_dpi,
     const float* __restrict__ W1_ppi, const float* __restrict__ b1_ppi,
     float* __restrict__ h_d, float* __restrict__ h_p,
     int nd, int np, int nbd) {
    __shared__ float2 xs1[16][64];
    __shared__ float2 xs2[16][64];
    int tid = threadIdx.x, wid = tid >> 5, lane = tid & 31;
    bool drug = (int)blockIdx.x < nbd;
    int row0 = (drug ? blockIdx.x : blockIdx.x - nbd) * 16;
    int n = drug ? nd : np;

    int r0 = wid * 2, r1 = r0 + 1;
    int node0 = row0 + r0, node1 = row0 + r1;

    if (drug) {
        int b0, d0, b1, d1;
        node_range(g_rowptr[0], node0, n, b0, d0);
        node_range(g_rowptr[0], node1, n, b1, d1);
        float4 m0, m1;
        gpair128h(g_esrc[0], g_xh_d, b0, d0, b1, d1, lane, m0, m1);
        xs1[r0][2 * lane]     = make_float2(m0.x, m0.y);
        xs1[r0][2 * lane + 1] = make_float2(m0.z, m0.w);
        xs1[r1][2 * lane]     = make_float2(m1.x, m1.y);
        xs1[r1][2 * lane + 1] = make_float2(m1.z, m1.w);
    } else {
        int b0, d0, b1, d1;
        node_range(g_rowptr[1], node0, n, b0, d0);
        node_range(g_rowptr[1], node1, n, b1, d1);
        float4 m0, m1;
        gpair128h(g_esrc[1], g_xh_d, b0, d0, b1, d1, lane, m0, m1);
        xs1[r0][2 * lane]     = make_float2(m0.x, m0.y);
        xs1[r0][2 * lane + 1] = make_float2(m0.z, m0.w);
        xs1[r1][2 * lane]     = make_float2(m1.x, m1.y);
        xs1[r1][2 * lane + 1] = make_float2(m1.z, m1.w);

        node_range(g_rowptr[2], node0, n, b0, d0);
        node_range(g_rowptr[2], node1, n, b1, d1);
        gpair128h(g_esrc[2], g_xh_p, b0, d0, b1, d1, lane, m0, m1);
        xs2[r0][2 * lane]     = make_float2(m0.x, m0.y);
        xs2[r0][2 * lane + 1] = make_float2(m0.z, m0.w);
        xs2[r1][2 * lane]     = make_float2(m1.x, m1.y);
        xs2[r1][2 * lane + 1] = make_float2(m1.z, m1.w);
    }
    __syncthreads();

    int j = tid & 127;
    int half = tid >> 7;
    int rbase = half * 8;
    ull acc[8];
#pragma unroll
    for (int p = 0; p < 8; p++) acc[p] = 0ull;

    if (drug) {
        for (int kk = 0; kk < 64; kk++) {
            ull wv = pack2(__ldg(W1_ddi + (2 * kk) * 128 + j),
                           __ldg(W1_ddi + (2 * kk + 1) * 128 + j));
#pragma unroll
            for (int p = 0; p < 8; p++)
                acc[p] = ffma2(*reinterpret_cast<const ull*>(&xs1[rbase + p][kk]), wv, acc[p]);
        }
        float bb = __ldg(b1_ddi + j);
#pragma unroll
        for (int p = 0; p < 8; p++) {
            float lo, hi;
            unpack2(acc[p], lo, hi);
            int r = row0 + rbase + p;
            if (r < n) h_d[(size_t)r * 128 + j] = lo + hi + bb;
        }
    } else {
        for (int kk = 0; kk < 64; kk++) {
            ull wv1 = pack2(__ldg(W1_dpi + (2 * kk) * 128 + j),
                            __ldg(W1_dpi + (2 * kk + 1) * 128 + j));
            ull wv2 = pack2(__ldg(W1_ppi + (2 * kk) * 128 + j),
                            __ldg(W1_ppi + (2 * kk + 1) * 128 + j));
#pragma unroll
            for (int p = 0; p < 8; p++) {
                acc[p] = ffma2(*reinterpret_cast<const ull*>(&xs1[rbase + p][kk]), wv1, acc[p]);
                acc[p] = ffma2(*reinterpret_cast<const ull*>(&xs2[rbase + p][kk]), wv2, acc[p]);
            }
        }
        float bb = __ldg(b1_dpi + j) + __ldg(b1_ppi + j);
#pragma unroll
        for (int p = 0; p < 8; p++) {
            float lo, hi;
            unpack2(acc[p], lo, hi);
            int r = row0 + rbase + p;
            if (r < n) h_p[(size_t)r * 128 + j] = lo + hi + bb;
        }
    }
}

// ---------------- merged layer-2 GEMM (fp16 output) ----------------

__global__ void __launch_bounds__(128)
k_gemm2(const float* __restrict__ h_d, const float* __restrict__ h_p,
        const float* __restrict__ W2_ddi, const float* __restrict__ W2_dpi,
        const float* __restrict__ W2_ppi,
        int nd, int np, int nbd) {
    __shared__ float2 xs[128][2][9];
    int tid = threadIdx.x;
    bool drug = (int)blockIdx.x < nbd;

    if (drug) {
        int row0 = blockIdx.x * 16;
#pragma unroll
        for (int p = 0; p < 8; p++) {
            int r0 = row0 + p, r1 = row0 + p + 8;
            float v0 = (r0 < nd) ? h_d[(size_t)r0 * 128 + tid] : 0.f;
            float v1 = (r1 < nd) ? h_d[(size_t)r1 * 128 + tid] : 0.f;
            xs[tid][0][p] = make_float2(v0, v1);
        }
        __syncthreads();
        const float* W = (tid < 64) ? W2_ddi : W2_dpi;
        __half* o = (tid < 64) ? g_th[0] : g_th[1];
        int c = tid & 63;
        ull acc[8];
#pragma unroll
        for (int p = 0; p < 8; p++) acc[p] = 0ull;
        for (int k = 0; k < 128; k++) {
            float wv = __ldg(W + k * 64 + c);
            ull wv2 = pack2(wv, wv);
            const ull* row = reinterpret_cast<const ull*>(&xs[k][0][0]);
#pragma unroll
            for (int p = 0; p < 8; p++) acc[p] = ffma2(row[p], wv2, acc[p]);
        }
#pragma unroll
        for (int p = 0; p < 8; p++) {
            float lo, hi;
            unpack2(acc[p], lo, hi);
            int r0 = row0 + p, r1 = row0 + p + 8;
            if (r0 < nd) o[(size_t)r0 * 64 + c] = __float2half(lo);
            if (r1 < nd) o[(size_t)r1 * 64 + c] = __float2half(hi);
        }
    } else {
        int row0 = (blockIdx.x - nbd) * 32;
#pragma unroll
        for (int g = 0; g < 2; g++) {
#pragma unroll
            for (int p = 0; p < 8; p++) {
                int r0 = row0 + g * 16 + p, r1 = row0 + g * 16 + p + 8;
                float v0 = (r0 < np) ? h_p[(size_t)r0 * 128 + tid] : 0.f;
                float v1 = (r1 < np) ? h_p[(size_t)r1 * 128 + tid] : 0.f;
                xs[tid][g][p] = make_float2(v0, v1);
            }
        }
        __syncthreads();
        int g = tid >> 6;
        int c = tid & 63;
        ull acc[8];
#pragma unroll
        for (int p = 0; p < 8; p++) acc[p] = 0ull;
        for (int k = 0; k < 128; k++) {
            float wv = __ldg(W2_ppi + k * 64 + c);
            ull wv2 = pack2(wv, wv);
            const ull* row = reinterpret_cast<const ull*>(&xs[k][g][0]);
#pragma unroll
            for (int p = 0; p < 8; p++) acc[p] = ffma2(row[p], wv2, acc[p]);
        }
#pragma unroll
        for (int p = 0; p < 8; p++) {
            float lo, hi;
            unpack2(acc[p], lo, hi);
            int r0 = row0 + g * 16 + p, r1 = row0 + g * 16 + p + 8;
            if (r0 < np) g_th[2][(size_t)r0 * 64 + c] = __float2half(lo);
            if (r1 < np) g_th[2][(size_t)r1 * 64 + c] = __float2half(hi);
        }
    }
}

// ---------------- merged layer-2 gather + bias + concat ----------------

__global__ void __launch_bounds__(256)
k_out(const float* __restrict__ b2_ddi, const float* __restrict__ b2_dpi,
      const float* __restrict__ b2_ppi,
      float* __restrict__ out, int nd, int np, int wd) {
    int gw = blockIdx.x * 8 + (threadIdx.x >> 5);
    int lane = threadIdx.x & 31;
    if (gw < wd) {
        int node0 = gw * 2, node1 = node0 + 1;
        int b0, d0, b1, d1;
        node_range(g_rowptr[0], node0, nd, b0, d0);
        node_range(g_rowptr[0], node1, nd, b1, d1);
        float2 m0, m1;
        gpair64h(g_esrc[0], g_th[0], b0, d0, b1, d1, lane, m0, m1);
        float2 bb = __ldg(reinterpret_cast<const float2*>(b2_ddi) + lane);
        if (node0 < nd)
            *(reinterpret_cast<float2*>(out + (size_t)node0 * 64) + lane) =
                make_float2(m0.x + bb.x, m0.y + bb.y);
        if (node1 < nd)
            *(reinterpret_cast<float2*>(out + (size_t)node1 * 64) + lane) =
                make_float2(m1.x + bb.x, m1.y + bb.y);
    } else {
        int node0 = (gw - wd) * 2, node1 = node0 + 1;
        int b0, d0, b1, d1;
        node_range(g_rowptr[1], node0, np, b0, d0);
        node_range(g_rowptr[1], node1, np, b1, d1);
        float2 ma0, ma1;
        gpair64h(g_esrc[1], g_th[1], b0, d0, b1, d1, lane, ma0, ma1);
        node_range(g_rowptr[2], node0, np, b0, d0);
        node_range(g_rowptr[2], node1, np, b1, d1);
        float2 mb0, mb1;
        gpair64h(g_esrc[2], g_th[2], b0, d0, b1, d1, lane, mb0, mb1);
        float2 ba = __ldg(reinterpret_cast<const float2*>(b2_dpi) + lane);
        float2 bb = __ldg(reinterpret_cast<const float2*>(b2_ppi) + lane);
        float bx = ba.x + bb.x, by = ba.y + bb.y;
        if (node0 < np)
            *(reinterpret_cast<float2*>(out + (size_t)(nd + node0) * 64) + lane) =
                make_float2(ma0.x + mb0.x + bx, ma0.y + mb0.y + by);
        if (node1 < np)
            *(reinterpret_cast<float2*>(out + (size_t)(nd + node1) * 64) + lane) =
                make_float2(ma1.x + mb1.x + bx, ma1.y + mb1.y + by);
    }
}

// ---------------- host launcher ----------------

static float* fs_ptr() {
    static float* p = nullptr;
    if (!p) cudaGetSymbolAddress((void**)&p, g_fs);
    return p;
}

static inline int cdiv(long long a, long long b) { return (int)((a + b - 1) / b); }

extern "C" void kernel_launch(void* const* d_in, const int* in_sizes, int n_in,
                              void* d_out, int out_size) {
    const float* x_drug = (const float*)d_in[0];
    const float* x_prot = (const float*)d_in[1];
    const int* src_ddi = (const int*)d_in[2];
    const int* dst_ddi = (const int*)d_in[3];
    const int* src_dpi = (const int*)d_in[4];
    const int* dst_dpi = (const int*)d_in[5];
    const int* src_ppi = (const int*)d_in[6];
    const int* dst_ppi = (const int*)d_in[7];
    const float* W1_ddi = (const float*)d_in[8];
    const float* b1_ddi = (const float*)d_in[9];
    const float* W1_dpi = (const float*)d_in[10];
    const float* b1_dpi = (const float*)d_in[11];
    const float* W1_ppi = (const float*)d_in[12];
    const float* b1_ppi = (const float*)d_in[13];
    const float* W2_ddi = (const float*)d_in[14];
    const float* b2_ddi = (const float*)d_in[15];
    const float* W2_dpi = (const float*)d_in[16];
    const float* b2_dpi = (const float*)d_in[17];
    const float* W2_ppi = (const float*)d_in[18];
    const float* b2_ppi = (const float*)d_in[19];
    float* out = (float*)d_out;

    int nd = in_sizes[0] / 128;
    int np = in_sizes[1] / 128;
    int ed = in_sizes[2];
    int ep = in_sizes[4];
    int eq = in_sizes[6];

    float* S = fs_ptr();
    float* h_d = S + F_HD;
    float* h_p = S + F_HP;

    // ---- CSR build + fp16 conversion ----
    k_zero_counts<<<cdiv(3 * (NMAX + 1), 256), 256>>>();
    int emax = ed > ep ? ed : ep;
    if (eq > emax) emax = eq;
    k_count<<<cdiv(emax, 256), 256>>>(dst_ddi, ed, dst_dpi, ep, dst_ppi, eq);
    k_tohalf<<<cdiv((long long)(nd > np ? nd : np) * 32, 256), 256>>>(
        x_drug, x_prot, nd * 32, np * 32);
    k_scan<<<3, 1024>>>(nd, np, np);
    k_fill3<<<cdiv(emax, 256), 256>>>(src_ddi, dst_ddi, ed,
                                      src_dpi, dst_dpi, ep,
                                      src_ppi, dst_ppi, eq);

    // ---- layer 1: fused gather (fp16 payload) + GEMM ----
    int nbd1 = cdiv(nd, 16), nbp1 = cdiv(np, 16);
    k_l1<<<nbd1 + nbp1, 256>>>(W1_ddi, b1_ddi, W1_dpi, b1_dpi, W1_ppi, b1_ppi,
                               h_d, h_p, nd, np, nbd1);

    // ---- layer 2 transforms (fp16 outputs) ----
    int nbd2 = cdiv(nd, 16), nbp2 = cdiv(np, 32);
    k_gemm2<<<nbd2 + nbp2, 128>>>(h_d, h_p, W2_ddi, W2_dpi, W2_ppi, nd, np, nbd2);

    // ---- layer 2 gather (fp16 payload) + bias + concat ----
    int wd = cdiv(nd, 2), wp = cdiv(np, 2);
    k_out<<<cdiv(wd + wp, 8), 256>>>(b2_ddi, b2_dpi, b2_ppi, out, nd, np, wd);
}

// round 7
// speedup vs baseline: 1.2018x; 1.2018x over previous
#include <cuda_runtime.h>
#include <stdint.h>

#define NMAX 50000
#define EMAX 600000
#define SCAN_BLK 2048   // elements per scan block (1024 threads x 2)
#define MAX_SBLK 32     // max scan blocks per relation (50000/2048 -> 25)

typedef unsigned long long ull;

// ---------------- CSR scratch ----------------
__device__ int g_rowptr[3][NMAX + 1];
__device__ int g_cursor[3][NMAX];
__device__ int g_esrc[3][EMAX];
__device__ int g_bsum[3][MAX_SBLK];
__device__ int g_boff[3][MAX_SBLK];
__device__ int g_total[3];

// ---------------- float scratch ----------------
constexpr size_t F_HD    = 0;                                  // [ND,128]
constexpr size_t F_HP    = F_HD    + (size_t)NMAX * 128;       // [NP,128]
constexpr size_t F_T_DDI = F_HP    + (size_t)NMAX * 128;       // [ND,64]
constexpr size_t F_T_DPI = F_T_DDI + (size_t)NMAX * 64;
constexpr size_t F_T_PPI = F_T_DPI + (size_t)NMAX * 64;
constexpr size_t F_TOTAL = F_T_PPI + (size_t)NMAX * 64;

__device__ float g_fs[F_TOTAL];

// ---------------- packed f32x2 helpers ----------------
__device__ __forceinline__ ull ffma2(ull a, ull b, ull c) {
    ull d;
    asm("fma.rn.f32x2 %0, %1, %2, %3;" : "=l"(d) : "l"(a), "l"(b), "l"(c));
    return d;
}
__device__ __forceinline__ ull pack2(float lo, float hi) {
    ull d;
    asm("mov.b64 %0, {%1, %2};" : "=l"(d) : "f"(lo), "f"(hi));
    return d;
}
__device__ __forceinline__ void unpack2(ull v, float& lo, float& hi) {
    asm("mov.b64 {%0, %1}, %2;" : "=f"(lo), "=f"(hi) : "l"(v));
}

// ---------------- CSR build ----------------

__global__ void k_zero_counts() {
    int i = blockIdx.x * blockDim.x + threadIdx.x;
    int total = 3 * (NMAX + 1);
    int stride = gridDim.x * blockDim.x;
    int* p = &g_rowptr[0][0];
    for (; i < total; i += stride) p[i] = 0;
}

__global__ void k_count(const int* __restrict__ d0, int e0,
                        const int* __restrict__ d1, int e1,
                        const int* __restrict__ d2, int e2) {
    int i = blockIdx.x * blockDim.x + threadIdx.x;
    int stride = gridDim.x * blockDim.x;
    for (int j = i; j < e0; j += stride) atomicAdd(&g_rowptr[0][__ldg(d0 + j)], 1);
    for (int j = i; j < e1; j += stride) atomicAdd(&g_rowptr[1][__ldg(d1 + j)], 1);
    for (int j = i; j < e2; j += stride) atomicAdd(&g_rowptr[2][__ldg(d2 + j)], 1);
}

// ---- 3-phase parallel scan ----
// Phase 1: per-block exclusive scan of SCAN_BLK counts; write block total.
// Grid = 3 * sblk; 1024 threads, 2 elements each.
__global__ void __launch_bounds__(1024)
k_scan1(int sblk, int n0, int n1, int n2) {
    __shared__ int sh[1024];
    int rel = blockIdx.x / sblk;
    int blk = blockIdx.x % sblk;
    int n = (rel == 0) ? n0 : ((rel == 1) ? n1 : n2);
    int* cnt = g_rowptr[rel];
    int tid = threadIdx.x;
    int base = blk * SCAN_BLK + tid * 2;
    int c0 = (base < n)     ? cnt[base]     : 0;
    int c1 = (base + 1 < n) ? cnt[base + 1] : 0;
    sh[tid] = c0 + c1;
    __syncthreads();
    for (int off = 1; off < 1024; off <<= 1) {
        int v = (tid >= off) ? sh[tid - off] : 0;
        __syncthreads();
        sh[tid] += v;
        __syncthreads();
    }
    int toff = (tid > 0) ? sh[tid - 1] : 0;
    if (base < n)     cnt[base]     = toff;
    if (base + 1 < n) cnt[base + 1] = toff + c0;
    if (tid == 1023) g_bsum[rel][blk] = sh[1023];
}

// Phase 2: scan the per-relation block sums (one warp per relation).
__global__ void k_scan2(int sblk) {
    int rel = threadIdx.x >> 5;
    int lane = threadIdx.x & 31;
    if (rel >= 3) return;
    int v = (lane < sblk) ? g_bsum[rel][lane] : 0;
    int orig = v;
#pragma unroll
    for (int off = 1; off < 32; off <<= 1) {
        int u = __shfl_up_sync(0xFFFFFFFF, v, off);
        if (lane >= off) v += u;
    }
    if (lane < sblk) g_boff[rel][lane] = v - orig;   // exclusive
    if (lane == 31) g_total[rel] = v;
}

// Phase 3: add block offsets; fill cursor; write rowptr[n].
__global__ void k_scan3(int sblk, int n0, int n1, int n2) {
    int i = blockIdx.x * blockDim.x + threadIdx.x;
    int stride = gridDim.x * blockDim.x;
    int total = 3 * NMAX;
    for (int t = i; t < total; t += stride) {
        int rel = t / NMAX;
        int idx = t % NMAX;
        int n = (rel == 0) ? n0 : ((rel == 1) ? n1 : n2);
        if (idx < n) {
            int v = g_rowptr[rel][idx] + g_boff[rel][idx / SCAN_BLK];
            g_rowptr[rel][idx] = v;
            g_cursor[rel][idx] = v;
        }
        if (idx == 0) g_rowptr[rel][n] = g_total[rel];
    }
}

__global__ void k_fill3(const int* __restrict__ s0, const int* __restrict__ d0, int e0,
                        const int* __restrict__ s1, const int* __restrict__ d1, int e1,
                        const int* __restrict__ s2, const int* __restrict__ d2, int e2) {
    int i = blockIdx.x * blockDim.x + threadIdx.x;
    int stride = gridDim.x * blockDim.x;
    for (int e = i; e < e0; e += stride) {
        int pos = atomicAdd(&g_cursor[0][__ldg(d0 + e)], 1);
        g_esrc[0][pos] = __ldg(s0 + e);
    }
    for (int e = i; e < e1; e += stride) {
        int pos = atomicAdd(&g_cursor[1][__ldg(d1 + e)], 1);
        g_esrc[1][pos] = __ldg(s1 + e);
    }
    for (int e = i; e < e2; e += stride) {
        int pos = atomicAdd(&g_cursor[2][__ldg(d2 + e)], 1);
        g_esrc[2][pos] = __ldg(s2 + e);
    }
}

// ---------------- pair-interleaved gather primitives ----------------

__device__ __forceinline__ void gpair128(const int* __restrict__ es,
                                         const float* __restrict__ x,
                                         int b0, int d0, int b1, int d1, int lane,
                                         float4& o0, float4& o1) {
    float4 a0 = make_float4(0.f, 0.f, 0.f, 0.f);
    float4 a1 = make_float4(0.f, 0.f, 0.f, 0.f);
    int m = d0 > d1 ? d0 : d1;
    for (int e = 0; e < m; e += 4) {
        float4 v0[4], v1[4];
#pragma unroll
        for (int j = 0; j < 4; j++) {
            bool q0 = (e + j) < d0;
            bool q1 = (e + j) < d1;
            int s0 = q0 ? __ldg(es + b0 + e + j) : 0;
            int s1 = q1 ? __ldg(es + b1 + e + j) : 0;
            v0[j] = q0 ? __ldg(reinterpret_cast<const float4*>(x + (size_t)s0 * 128) + lane)
                       : make_float4(0.f, 0.f, 0.f, 0.f);
            v1[j] = q1 ? __ldg(reinterpret_cast<const float4*>(x + (size_t)s1 * 128) + lane)
                       : make_float4(0.f, 0.f, 0.f, 0.f);
        }
#pragma unroll
        for (int j = 0; j < 4; j++) {
            a0.x += v0[j].x; a0.y += v0[j].y; a0.z += v0[j].z; a0.w += v0[j].w;
            a1.x += v1[j].x; a1.y += v1[j].y; a1.z += v1[j].z; a1.w += v1[j].w;
        }
    }
    float i0 = 1.0f / fmaxf((float)d0, 1.0f);
    float i1 = 1.0f / fmaxf((float)d1, 1.0f);
    o0 = make_float4(a0.x * i0, a0.y * i0, a0.z * i0, a0.w * i0);
    o1 = make_float4(a1.x * i1, a1.y * i1, a1.z * i1, a1.w * i1);
}

__device__ __forceinline__ void gpair64(const int* __restrict__ es,
                                        const float* __restrict__ x,
                                        int b0, int d0, int b1, int d1, int lane,
                                        float2& o0, float2& o1) {
    float2 a0 = make_float2(0.f, 0.f);
    float2 a1 = make_float2(0.f, 0.f);
    int m = d0 > d1 ? d0 : d1;
    for (int e = 0; e < m; e += 4) {
        float2 v0[4], v1[4];
#pragma unroll
        for (int j = 0; j < 4; j++) {
            bool q0 = (e + j) < d0;
            bool q1 = (e + j) < d1;
            int s0 = q0 ? __ldg(es + b0 + e + j) : 0;
            int s1 = q1 ? __ldg(es + b1 + e + j) : 0;
            v0[j] = q0 ? __ldg(reinterpret_cast<const float2*>(x + (size_t)s0 * 64) + lane)
                       : make_float2(0.f, 0.f);
            v1[j] = q1 ? __ldg(reinterpret_cast<const float2*>(x + (size_t)s1 * 64) + lane)
                       : make_float2(0.f, 0.f);
        }
#pragma unroll
        for (int j = 0; j < 4; j++) {
            a0.x += v0[j].x; a0.y += v0[j].y;
            a1.x += v1[j].x; a1.y += v1[j].y;
        }
    }
    float i0 = 1.0f / fmaxf((float)d0, 1.0f);
    float i1 = 1.0f / fmaxf((float)d1, 1.0f);
    o0 = make_float2(a0.x * i0, a0.y * i0);
    o1 = make_float2(a1.x * i1, a1.y * i1);
}

__device__ __forceinline__ void node_range(const int* __restrict__ ptr, int node, int n,
                                           int& b, int& d) {
    if (node < n) {
        b = ptr[node];
        d = ptr[node + 1] - b;
    } else {
        b = 0; d = 0;
    }
}

// ---------------- merged fused layer-1 ----------------

__global__ void __launch_bounds__(256, 3)
k_l1(const float* __restrict__ xd, const float* __restrict__ xp,
     const float* __restrict__ W1_ddi, const float* __restrict__ b1_ddi,
     const float* __restrict__ W1_dpi, const float* __restrict__ b1_dpi,
     const float* __restrict__ W1_ppi, const float* __restrict__ b1_ppi,
     float* __restrict__ h_d, float* __restrict__ h_p,
     int nd, int np, int nbd) {
    __shared__ float2 xs1[16][64];
    __shared__ float2 xs2[16][64];
    int tid = threadIdx.x, wid = tid >> 5, lane = tid & 31;
    bool drug = (int)blockIdx.x < nbd;
    int row0 = (drug ? blockIdx.x : blockIdx.x - nbd) * 16;
    int n = drug ? nd : np;

    int r0 = wid * 2, r1 = r0 + 1;
    int node0 = row0 + r0, node1 = row0 + r1;

    if (drug) {
        int b0, d0, b1, d1;
        node_range(g_rowptr[0], node0, n, b0, d0);
        node_range(g_rowptr[0], node1, n, b1, d1);
        float4 m0, m1;
        gpair128(g_esrc[0], xd, b0, d0, b1, d1, lane, m0, m1);
        xs1[r0][2 * lane]     = make_float2(m0.x, m0.y);
        xs1[r0][2 * lane + 1] = make_float2(m0.z, m0.w);
        xs1[r1][2 * lane]     = make_float2(m1.x, m1.y);
        xs1[r1][2 * lane + 1] = make_float2(m1.z, m1.w);
    } else {
        int b0, d0, b1, d1;
        node_range(g_rowptr[1], node0, n, b0, d0);
        node_range(g_rowptr[1], node1, n, b1, d1);
        float4 m0, m1;
        gpair128(g_esrc[1], xd, b0, d0, b1, d1, lane, m0, m1);
        xs1[r0][2 * lane]     = make_float2(m0.x, m0.y);
        xs1[r0][2 * lane + 1] = make_float2(m0.z, m0.w);
        xs1[r1][2 * lane]     = make_float2(m1.x, m1.y);
        xs1[r1][2 * lane + 1] = make_float2(m1.z, m1.w);

        node_range(g_rowptr[2], node0, n, b0, d0);
        node_range(g_rowptr[2], node1, n, b1, d1);
        gpair128(g_esrc[2], xp, b0, d0, b1, d1, lane, m0, m1);
        xs2[r0][2 * lane]     = make_float2(m0.x, m0.y);
        xs2[r0][2 * lane + 1] = make_float2(m0.z, m0.w);
        xs2[r1][2 * lane]     = make_float2(m1.x, m1.y);
        xs2[r1][2 * lane + 1] = make_float2(m1.z, m1.w);
    }
    __syncthreads();

    int j = tid & 127;
    int half = tid >> 7;
    int rbase = half * 8;
    ull acc[8];
#pragma unroll
    for (int p = 0; p < 8; p++) acc[p] = 0ull;

    if (drug) {
        for (int kk = 0; kk < 64; kk++) {
            ull wv = pack2(__ldg(W1_ddi + (2 * kk) * 128 + j),
                           __ldg(W1_ddi + (2 * kk + 1) * 128 + j));
#pragma unroll
            for (int p = 0; p < 8; p++)
                acc[p] = ffma2(*reinterpret_cast<const ull*>(&xs1[rbase + p][kk]), wv, acc[p]);
        }
        float bb = __ldg(b1_ddi + j);
#pragma unroll
        for (int p = 0; p < 8; p++) {
            float lo, hi;
            unpack2(acc[p], lo, hi);
            int r = row0 + rbase + p;
            if (r < n) h_d[(size_t)r * 128 + j] = lo + hi + bb;
        }
    } else {
        for (int kk = 0; kk < 64; kk++) {
            ull wv1 = pack2(__ldg(W1_dpi + (2 * kk) * 128 + j),
                            __ldg(W1_dpi + (2 * kk + 1) * 128 + j));
            ull wv2 = pack2(__ldg(W1_ppi + (2 * kk) * 128 + j),
                            __ldg(W1_ppi + (2 * kk + 1) * 128 + j));
#pragma unroll
            for (int p = 0; p < 8; p++) {
                acc[p] = ffma2(*reinterpret_cast<const ull*>(&xs1[rbase + p][kk]), wv1, acc[p]);
                acc[p] = ffma2(*reinterpret_cast<const ull*>(&xs2[rbase + p][kk]), wv2, acc[p]);
            }
        }
        float bb = __ldg(b1_dpi + j) + __ldg(b1_ppi + j);
#pragma unroll
        for (int p = 0; p < 8; p++) {
            float lo, hi;
            unpack2(acc[p], lo, hi);
            int r = row0 + rbase + p;
            if (r < n) h_p[(size_t)r * 128 + j] = lo + hi + bb;
        }
    }
}

// ---------------- merged layer-2 GEMM ----------------

__global__ void __launch_bounds__(128)
k_gemm2(const float* __restrict__ h_d, const float* __restrict__ h_p,
        const float* __restrict__ W2_ddi, const float* __restrict__ W2_dpi,
        const float* __restrict__ W2_ppi,
        float* __restrict__ t_ddi, float* __restrict__ t_dpi,
        float* __restrict__ t_ppi, int nd, int np, int nbd) {
    __shared__ float2 xs[128][2][9];
    int tid = threadIdx.x;
    bool drug = (int)blockIdx.x < nbd;

    if (drug) {
        int row0 = blockIdx.x * 16;
#pragma unroll
        for (int p = 0; p < 8; p++) {
            int r0 = row0 + p, r1 = row0 + p + 8;
            float v0 = (r0 < nd) ? h_d[(size_t)r0 * 128 + tid] : 0.f;
            float v1 = (r1 < nd) ? h_d[(size_t)r1 * 128 + tid] : 0.f;
            xs[tid][0][p] = make_float2(v0, v1);
        }
        __syncthreads();
        const float* W = (tid < 64) ? W2_ddi : W2_dpi;
        float* o = (tid < 64) ? t_ddi : t_dpi;
        int c = tid & 63;
        ull acc[8];
#pragma unroll
        for (int p = 0; p < 8; p++) acc[p] = 0ull;
        for (int k = 0; k < 128; k++) {
            float wv = __ldg(W + k * 64 + c);
            ull wv2 = pack2(wv, wv);
            const ull* row = reinterpret_cast<const ull*>(&xs[k][0][0]);
#pragma unroll
            for (int p = 0; p < 8; p++) acc[p] = ffma2(row[p], wv2, acc[p]);
        }
#pragma unroll
        for (int p = 0; p < 8; p++) {
            float lo, hi;
            unpack2(acc[p], lo, hi);
            int r0 = row0 + p, r1 = row0 + p + 8;
            if (r0 < nd) o[(size_t)r0 * 64 + c] = lo;
            if (r1 < nd) o[(size_t)r1 * 64 + c] = hi;
        }
    } else {
        int row0 = (blockIdx.x - nbd) * 32;
#pragma unroll
        for (int g = 0; g < 2; g++) {
#pragma unroll
            for (int p = 0; p < 8; p++) {
                int r0 = row0 + g * 16 + p, r1 = row0 + g * 16 + p + 8;
                float v0 = (r0 < np) ? h_p[(size_t)r0 * 128 + tid] : 0.f;
                float v1 = (r1 < np) ? h_p[(size_t)r1 * 128 + tid] : 0.f;
                xs[tid][g][p] = make_float2(v0, v1);
            }
        }
        __syncthreads();
        int g = tid >> 6;
        int c = tid & 63;
        ull acc[8];
#pragma unroll
        for (int p = 0; p < 8; p++) acc[p] = 0ull;
        for (int k = 0; k < 128; k++) {
            float wv = __ldg(W2_ppi + k * 64 + c);
            ull wv2 = pack2(wv, wv);
            const ull* row = reinterpret_cast<const ull*>(&xs[k][g][0]);
#pragma unroll
            for (int p = 0; p < 8; p++) acc[p] = ffma2(row[p], wv2, acc[p]);
        }
#pragma unroll
        for (int p = 0; p < 8; p++) {
            float lo, hi;
            unpack2(acc[p], lo, hi);
            int r0 = row0 + g * 16 + p, r1 = row0 + g * 16 + p + 8;
            if (r0 < np) t_ppi[(size_t)r0 * 64 + c] = lo;
            if (r1 < np) t_ppi[(size_t)r1 * 64 + c] = hi;
        }
    }
}

// ---------------- merged layer-2 gather + bias + concat ----------------

__global__ void __launch_bounds__(256)
k_out(const float* __restrict__ t_ddi, const float* __restrict__ t_dpi,
      const float* __restrict__ t_ppi,
      const float* __restrict__ b2_ddi, const float* __restrict__ b2_dpi,
      const float* __restrict__ b2_ppi,
      float* __restrict__ out, int nd, int np, int wd) {
    int gw = blockIdx.x * 8 + (threadIdx.x >> 5);
    int lane = threadIdx.x & 31;
    if (gw < wd) {
        int node0 = gw * 2, node1 = node0 + 1;
        int b0, d0, b1, d1;
        node_range(g_rowptr[0], node0, nd, b0, d0);
        node_range(g_rowptr[0], node1, nd, b1, d1);
        float2 m0, m1;
        gpair64(g_esrc[0], t_ddi, b0, d0, b1, d1, lane, m0, m1);
        float2 bb = __ldg(reinterpret_cast<const float2*>(b2_ddi) + lane);
        if (node0 < nd)
            *(reinterpret_cast<float2*>(out + (size_t)node0 * 64) + lane) =
                make_float2(m0.x + bb.x, m0.y + bb.y);
        if (node1 < nd)
            *(reinterpret_cast<float2*>(out + (size_t)node1 * 64) + lane) =
                make_float2(m1.x + bb.x, m1.y + bb.y);
    } else {
        int node0 = (gw - wd) * 2, node1 = node0 + 1;
        int b0, d0, b1, d1;
        node_range(g_rowptr[1], node0, np, b0, d0);
        node_range(g_rowptr[1], node1, np, b1, d1);
        float2 ma0, ma1;
        gpair64(g_esrc[1], t_dpi, b0, d0, b1, d1, lane, ma0, ma1);
        node_range(g_rowptr[2], node0, np, b0, d0);
        node_range(g_rowptr[2], node1, np, b1, d1);
        float2 mb0, mb1;
        gpair64(g_esrc[2], t_ppi, b0, d0, b1, d1, lane, mb0, mb1);
        float2 ba = __ldg(reinterpret_cast<const float2*>(b2_dpi) + lane);
        float2 bb = __ldg(reinterpret_cast<const float2*>(b2_ppi) + lane);
        float bx = ba.x + bb.x, by = ba.y + bb.y;
        if (node0 < np)
            *(reinterpret_cast<float2*>(out + (size_t)(nd + node0) * 64) + lane) =
                make_float2(ma0.x + mb0.x + bx, ma0.y + mb0.y + by);
        if (node1 < np)
            *(reinterpret_cast<float2*>(out + (size_t)(nd + node1) * 64) + lane) =
                make_float2(ma1.x + mb1.x + bx, ma1.y + mb1.y + by);
    }
}

// ---------------- host launcher ----------------

static float* fs_ptr() {
    static float* p = nullptr;
    if (!p) cudaGetSymbolAddress((void**)&p, g_fs);
    return p;
}

static inline int cdiv(long long a, long long b) { return (int)((a + b - 1) / b); }

extern "C" void kernel_launch(void* const* d_in, const int* in_sizes, int n_in,
                              void* d_out, int out_size) {
    const float* x_drug = (const float*)d_in[0];
    const float* x_prot = (const float*)d_in[1];
    const int* src_ddi = (const int*)d_in[2];
    const int* dst_ddi = (const int*)d_in[3];
    const int* src_dpi = (const int*)d_in[4];
    const int* dst_dpi = (const int*)d_in[5];
    const int* src_ppi = (const int*)d_in[6];
    const int* dst_ppi = (const int*)d_in[7];
    const float* W1_ddi = (const float*)d_in[8];
    const float* b1_ddi = (const float*)d_in[9];
    const float* W1_dpi = (const float*)d_in[10];
    const float* b1_dpi = (const float*)d_in[11];
    const float* W1_ppi = (const float*)d_in[12];
    const float* b1_ppi = (const float*)d_in[13];
    const float* W2_ddi = (const float*)d_in[14];
    const float* b2_ddi = (const float*)d_in[15];
    const float* W2_dpi = (const float*)d_in[16];
    const float* b2_dpi = (const float*)d_in[17];
    const float* W2_ppi = (const float*)d_in[18];
    const float* b2_ppi = (const float*)d_in[19];
    float* out = (float*)d_out;

    int nd = in_sizes[0] / 128;
    int np = in_sizes[1] / 128;
    int ed = in_sizes[2];
    int ep = in_sizes[4];
    int eq = in_sizes[6];

    float* S = fs_ptr();
    float* h_d   = S + F_HD;
    float* h_p   = S + F_HP;
    float* t_ddi = S + F_T_DDI;
    float* t_dpi = S + F_T_DPI;
    float* t_ppi = S + F_T_PPI;

    // ---- CSR build ----
    k_zero_counts<<<cdiv(3 * (NMAX + 1), 256), 256>>>();
    int emax = ed > ep ? ed : ep;
    if (eq > emax) emax = eq;
    k_count<<<cdiv(emax, 256), 256>>>(dst_ddi, ed, dst_dpi, ep, dst_ppi, eq);

    int nmax = nd > np ? nd : np;
    int sblk = cdiv(nmax, SCAN_BLK);          // same partitioning for all rels
    k_scan1<<<3 * sblk, 1024>>>(sblk, nd, np, np);
    k_scan2<<<1, 96>>>(sblk);
    k_scan3<<<cdiv(3 * NMAX, 256), 256>>>(sblk, nd, np, np);

    k_fill3<<<cdiv(emax, 256), 256>>>(src_ddi, dst_ddi, ed,
                                      src_dpi, dst_dpi, ep,
                                      src_ppi, dst_ppi, eq);

    // ---- layer 1: fused gather + GEMM ----
    int nbd1 = cdiv(nd, 16), nbp1 = cdiv(np, 16);
    k_l1<<<nbd1 + nbp1, 256>>>(x_drug, x_prot,
                               W1_ddi, b1_ddi, W1_dpi, b1_dpi, W1_ppi, b1_ppi,
                               h_d, h_p, nd, np, nbd1);

    // ---- layer 2 transforms ----
    int nbd2 = cdiv(nd, 16), nbp2 = cdiv(np, 32);
    k_gemm2<<<nbd2 + nbp2, 128>>>(h_d, h_p, W2_ddi, W2_dpi, W2_ppi,
                                  t_ddi, t_dpi, t_ppi, nd, np, nbd2);

    // ---- layer 2 gather + bias + concat ----
    int wd = cdiv(nd, 2), wp = cdiv(np, 2);
    k_out<<<cdiv(wd + wp, 8), 256>>>(t_ddi, t_dpi, t_ppi,
                                     b2_ddi, b2_dpi, b2_ppi, out, nd, np, wd);
}